// round 9
// baseline (speedup 1.0000x reference)
#include <cuda_runtime.h>
#include <cuda_fp16.h>
#include <cstdint>

#define N_NODES   100000
#define N_EDGES   1600000
#define D         64
#define NEG_SLOPE 0.2f
#define BUCKET    64        // max in-degree slots (Poisson(16): P(>64) ~ 1e-29)

typedef unsigned long long ull;

// packed fp32x2 FMA (sm_103a FFMA2 — PTX-only pattern)
#define FMA2(d, a, b) \
    asm("fma.rn.f32x2 %0, %1, %2, %0;" : "+l"(d) : "l"(a), "l"(b))
#define UNPACK2(lo, hi, in) \
    asm("mov.b64 {%0, %1}, %2;" : "=f"(lo), "=f"(hi) : "l"(in))

__device__ __forceinline__ uint32_t h2_bits(__half2 h) {
    uint32_t u;
    memcpy(&u, &h, 4);
    return u;
}

// Scratch (allocation-free rule: __device__ globals)
__device__ int     g_cnt[N_NODES];                       // in-degree counters
__device__ float2  g_csr[(size_t)N_NODES * BUCKET];      // padded buckets (src, ex)
__device__ __half2 g_gh[(size_t)N_NODES * 32];           // feat @ W_neigh^T (fp16)

// ---------------------------------------------------------------------------
// K1: single-pass bucket build. pos = atomicAdd(cnt[d]); csr[d*64+pos]=(src,ex)
// ---------------------------------------------------------------------------
__global__ void place_kernel(const float* __restrict__ rel,
                             const float* __restrict__ attn,
                             const int*   __restrict__ src,
                             const int*   __restrict__ dst) {
    int i = (blockIdx.x * blockDim.x + threadIdx.x) * 2;
    if (i >= N_EDGES) return;
    float a0 = __ldg(&attn[0]);
    float a1 = __ldg(&attn[1]);
    float4 r = *reinterpret_cast<const float4*>(rel + i * 2);  // edges i, i+1
    int2 s2 = *reinterpret_cast<const int2*>(src + i);
    int2 d2 = *reinterpret_cast<const int2*>(dst + i);

    float e0 = r.x * a0 + r.y * a1;
    float e1 = r.z * a0 + r.w * a1;
    e0 = (e0 > 0.0f) ? e0 : NEG_SLOPE * e0;
    e1 = (e1 > 0.0f) ? e1 : NEG_SLOPE * e1;
    float ex0 = __expf(e0);
    float ex1 = __expf(e1);

    int p0 = atomicAdd(&g_cnt[d2.x], 1);
    int p1 = atomicAdd(&g_cnt[d2.y], 1);
    if (p0 < BUCKET)
        g_csr[(size_t)d2.x * BUCKET + p0] = make_float2(__int_as_float(s2.x), ex0);
    if (p1 < BUCKET)
        g_csr[(size_t)d2.y * BUCKET + p1] = make_float2(__int_as_float(s2.y), ex1);
}

// ---------------------------------------------------------------------------
// K2: fused dual GEMM, issue-optimized.
//   Warp = 8 nodes x full 64-col space of ONE GEMM per half-warp:
//     lanes 0-15  -> self GEMM  (cols 4c..4c+3)
//     lanes 16-31 -> neigh GEMM (cols 4c..4c+3)
//   Feat loads are warp-uniform (broadcast LDS.128). Weights stored
//   DUPLICATED (w,w) split in two arrays so each lane's 4 cols are two
//   contiguous LDS.128. Per k: 4 LDS + 16 FMA2.
// ---------------------------------------------------------------------------
#define ROWF      68                      // floats per smem row (16B-aligned stride)
#define OFF_F     0
#define OFF_W1S   (64 * ROWF)
#define OFF_W2S   (2 * 64 * ROWF)
#define OFF_W1N   (3 * 64 * ROWF)
#define OFF_W2N   (4 * 64 * ROWF)
#define GEMM_SMEM_BYTES (5 * 64 * ROWF * 4)   // 87040 B

__global__ __launch_bounds__(256) void fused_gemm_kernel(
    const float* __restrict__ feat,
    const float* __restrict__ Ws, const float* __restrict__ bs,
    const float* __restrict__ Wn, const float* __restrict__ bn,
    float* __restrict__ out) {
    extern __shared__ float smem[];
    const int t = threadIdx.x;
    const int nodeBase = blockIdx.x * 64;

    // Weights: dup-store (w,w). Array1 holds cols {4c,4c+1}, array2 {4c+2,4c+3}.
    for (int i = t; i < 4096; i += 256) {
        int o = i >> 6, k = i & 63;
        int off = (o >> 2) * 4 + (o & 1) * 2;      // even -> 8B aligned
        int hi  = (o >> 1) & 1;
        float w = Ws[i];
        *reinterpret_cast<float2*>(
            &smem[(hi ? OFF_W2S : OFF_W1S) + k * ROWF + off]) = make_float2(w, w);
        w = Wn[i];
        *reinterpret_cast<float2*>(
            &smem[(hi ? OFF_W2N : OFF_W1N) + k * ROWF + off]) = make_float2(w, w);
    }
    // Feat tile: [k][n], non-duplicated.
    for (int i = t; i < 4096; i += 256) {
        int n = i >> 6, k = i & 63;
        int node = nodeBase + n;
        smem[OFF_F + k * ROWF + n] =
            (node < N_NODES) ? __ldg(&feat[(size_t)node * D + k]) : 0.f;
    }
    __syncthreads();

    const int lane = t & 31;
    const int w    = t >> 5;          // warp id: nodes w*8 .. w*8+7
    const int c    = lane & 15;       // column group (4 cols)
    const int gs   = lane >> 4;       // 0 = self GEMM, 1 = neigh GEMM
    const int nb   = w * 8;

    const float* fp = smem + OFF_F + nb;
    const float* w1 = smem + (gs ? OFF_W1N : OFF_W1S) + c * 4;
    const float* w2 = smem + (gs ? OFF_W2N : OFF_W2S) + c * 4;

    ull acc[4][4] = {};               // [node-pair][col]

    #pragma unroll 4
    for (int k = 0; k < 64; k++) {
        ulonglong2 fA = *reinterpret_cast<const ulonglong2*>(fp + k * ROWF);     // n0..n3
        ulonglong2 fB = *reinterpret_cast<const ulonglong2*>(fp + k * ROWF + 4); // n4..n7
        ulonglong2 wa = *reinterpret_cast<const ulonglong2*>(w1 + k * ROWF);     // (w0,w0),(w1,w1)
        ulonglong2 wb = *reinterpret_cast<const ulonglong2*>(w2 + k * ROWF);     // (w2,w2),(w3,w3)
        FMA2(acc[0][0], fA.x, wa.x); FMA2(acc[0][1], fA.x, wa.y);
        FMA2(acc[0][2], fA.x, wb.x); FMA2(acc[0][3], fA.x, wb.y);
        FMA2(acc[1][0], fA.y, wa.x); FMA2(acc[1][1], fA.y, wa.y);
        FMA2(acc[1][2], fA.y, wb.x); FMA2(acc[1][3], fA.y, wb.y);
        FMA2(acc[2][0], fB.x, wa.x); FMA2(acc[2][1], fB.x, wa.y);
        FMA2(acc[2][2], fB.x, wb.x); FMA2(acc[2][3], fB.x, wb.y);
        FMA2(acc[3][0], fB.y, wa.x); FMA2(acc[3][1], fB.y, wa.y);
        FMA2(acc[3][2], fB.y, wb.x); FMA2(acc[3][3], fB.y, wb.y);
    }

    float4 bias = make_float4(0.f, 0.f, 0.f, 0.f);
    if (gs == 0) {
        bias.x = __ldg(&bs[c * 4])     + __ldg(&bn[c * 4]);
        bias.y = __ldg(&bs[c * 4 + 1]) + __ldg(&bn[c * 4 + 1]);
        bias.z = __ldg(&bs[c * 4 + 2]) + __ldg(&bn[c * 4 + 2]);
        bias.w = __ldg(&bs[c * 4 + 3]) + __ldg(&bn[c * 4 + 3]);
    }

    #pragma unroll
    for (int j = 0; j < 4; j++) {
        int n0 = nodeBase + nb + 2 * j;
        int n1 = n0 + 1;
        float l0, h0, l1, h1, l2, h2, l3, h3;
        UNPACK2(l0, h0, acc[j][0]);
        UNPACK2(l1, h1, acc[j][1]);
        UNPACK2(l2, h2, acc[j][2]);
        UNPACK2(l3, h3, acc[j][3]);
        if (gs == 0) {
            if (n0 < N_NODES)
                reinterpret_cast<float4*>(out)[(size_t)n0 * 16 + c] =
                    make_float4(l0 + bias.x, l1 + bias.y, l2 + bias.z, l3 + bias.w);
            if (n1 < N_NODES)
                reinterpret_cast<float4*>(out)[(size_t)n1 * 16 + c] =
                    make_float4(h0 + bias.x, h1 + bias.y, h2 + bias.z, h3 + bias.w);
        } else {
            if (n0 < N_NODES)
                *reinterpret_cast<uint2*>(&g_gh[(size_t)n0 * 32 + c * 2]) =
                    make_uint2(h2_bits(__floats2half2_rn(l0, l1)),
                               h2_bits(__floats2half2_rn(l2, l3)));
            if (n1 < N_NODES)
                *reinterpret_cast<uint2*>(&g_gh[(size_t)n1 * 32 + c * 2]) =
                    make_uint2(h2_bits(__floats2half2_rn(h0, h1)),
                               h2_bits(__floats2half2_rn(h2, h3)));
        }
    }
}

// ---------------------------------------------------------------------------
// K3: gather-aggregate. One warp per dst node; fp16 rows = 1 line/edge.
// ---------------------------------------------------------------------------
__global__ __launch_bounds__(256) void aggregate_kernel(float* __restrict__ out) {
    int warp = (blockIdx.x * blockDim.x + threadIdx.x) >> 5;
    if (warp >= N_NODES) return;
    const int lane = threadIdx.x & 31;

    int cnt = g_cnt[warp];
    if (cnt == 0) return;
    if (cnt > BUCKET) cnt = BUCKET;
    const float2* bucket = &g_csr[(size_t)warp * BUCKET];

    float ax = 0.f, ay = 0.f, sum = 0.f;

    int j = 0;
    for (; j + 4 <= cnt; j += 4) {
        float2 p0 = __ldg(&bucket[j]);        // uniform addr: broadcast
        float2 p1 = __ldg(&bucket[j + 1]);
        float2 p2 = __ldg(&bucket[j + 2]);
        float2 p3 = __ldg(&bucket[j + 3]);
        __half2 h0 = __ldg(&g_gh[(size_t)__float_as_int(p0.x) * 32 + lane]);
        __half2 h1 = __ldg(&g_gh[(size_t)__float_as_int(p1.x) * 32 + lane]);
        __half2 h2 = __ldg(&g_gh[(size_t)__float_as_int(p2.x) * 32 + lane]);
        __half2 h3 = __ldg(&g_gh[(size_t)__float_as_int(p3.x) * 32 + lane]);
        float2 f0 = __half22float2(h0);
        float2 f1 = __half22float2(h1);
        float2 f2 = __half22float2(h2);
        float2 f3 = __half22float2(h3);
        sum += p0.y + p1.y + p2.y + p3.y;
        ax += p0.y * f0.x + p1.y * f1.x + p2.y * f2.x + p3.y * f3.x;
        ay += p0.y * f0.y + p1.y * f1.y + p2.y * f2.y + p3.y * f3.y;
    }
    for (; j < cnt; j++) {
        float2 p = __ldg(&bucket[j]);
        float2 f = __half22float2(
            __ldg(&g_gh[(size_t)__float_as_int(p.x) * 32 + lane]));
        sum += p.y;
        ax  += p.y * f.x;
        ay  += p.y * f.y;
    }

    const float inv = 1.0f / sum;
    float2* po = reinterpret_cast<float2*>(out) + (size_t)warp * 32 + lane;
    float2 cur = *po;
    cur.x += ax * inv;
    cur.y += ay * inv;
    *po = cur;
}

// ---------------------------------------------------------------------------
// Launch: memset + place (edge path) || GEMM (node path), join, aggregate
// ---------------------------------------------------------------------------
extern "C" void kernel_launch(void* const* d_in, const int* in_sizes, int n_in,
                              void* d_out, int out_size) {
    const float* feat = (const float*)d_in[0];
    const float* rel  = (const float*)d_in[1];
    const float* Ws   = (const float*)d_in[2];
    const float* bs   = (const float*)d_in[3];
    const float* Wn   = (const float*)d_in[4];
    const float* bn   = (const float*)d_in[5];
    const float* attn = (const float*)d_in[6];
    const int*   src  = (const int*)d_in[7];
    const int*   dst  = (const int*)d_in[8];
    float* out = (float*)d_out;

    static void*        cnt_addr = nullptr;
    static cudaStream_t s2;
    static cudaEvent_t  evFork, evJoin;
    if (!cnt_addr) {
        cudaFuncSetAttribute(fused_gemm_kernel,
                             cudaFuncAttributeMaxDynamicSharedMemorySize,
                             GEMM_SMEM_BYTES);
        cudaGetSymbolAddress(&cnt_addr, g_cnt);
        cudaStreamCreateWithFlags(&s2, cudaStreamNonBlocking);
        cudaEventCreateWithFlags(&evFork, cudaEventDisableTiming);
        cudaEventCreateWithFlags(&evJoin, cudaEventDisableTiming);
    }

    // Fork: GEMM (node path) on side stream
    cudaEventRecord(evFork, 0);
    cudaStreamWaitEvent(s2, evFork, 0);
    fused_gemm_kernel<<<(N_NODES + 63) / 64, 256, GEMM_SMEM_BYTES, s2>>>(
        feat, Ws, bs, Wn, bn, out);
    cudaEventRecord(evJoin, s2);

    // Edge path: zero counters, then single-pass bucket build
    cudaMemsetAsync(cnt_addr, 0, N_NODES * sizeof(int));
    place_kernel<<<(N_EDGES / 2 + 255) / 256, 256>>>(rel, attn, src, dst);

    // Join, then aggregate needs both paths
    cudaStreamWaitEvent(0, evJoin, 0);
    aggregate_kernel<<<(N_NODES * 32 + 255) / 256, 256>>>(out);
}

// round 10
// speedup vs baseline: 1.1375x; 1.1375x over previous
#include <cuda_runtime.h>
#include <cuda_fp16.h>
#include <cstdint>

#define N_NODES   100000
#define N_EDGES   1600000
#define D         64
#define NEG_SLOPE 0.2f
#define BUCKET    64        // max in-degree slots (Poisson(16): P(>64) ~ 1e-29)

typedef unsigned long long ull;

// packed fp32x2 FMA (sm_103a FFMA2 — PTX-only pattern)
#define FMA2(d, a, b) \
    asm("fma.rn.f32x2 %0, %1, %2, %0;" : "+l"(d) : "l"(a), "l"(b))
#define UNPACK2(lo, hi, in) \
    asm("mov.b64 {%0, %1}, %2;" : "=f"(lo), "=f"(hi) : "l"(in))

__device__ __forceinline__ uint32_t h2_bits(__half2 h) {
    uint32_t u;
    memcpy(&u, &h, 4);
    return u;
}

// Scratch (allocation-free rule: __device__ globals)
__device__ int     g_cnt[N_NODES];                       // in-degree counters
__device__ float2  g_csr[(size_t)N_NODES * BUCKET];      // padded buckets (src, ex)
__device__ __half2 g_gh[(size_t)N_NODES * 32];           // feat @ W_neigh^T (fp16)

// ---------------------------------------------------------------------------
// K1: single-pass bucket build. pos = atomicAdd(cnt[d]); csr[d*64+pos]=(src,ex)
// ---------------------------------------------------------------------------
__global__ void place_kernel(const float* __restrict__ rel,
                             const float* __restrict__ attn,
                             const int*   __restrict__ src,
                             const int*   __restrict__ dst) {
    int i = (blockIdx.x * blockDim.x + threadIdx.x) * 2;
    if (i >= N_EDGES) return;
    float a0 = __ldg(&attn[0]);
    float a1 = __ldg(&attn[1]);
    float4 r = *reinterpret_cast<const float4*>(rel + i * 2);  // edges i, i+1
    int2 s2 = *reinterpret_cast<const int2*>(src + i);
    int2 d2 = *reinterpret_cast<const int2*>(dst + i);

    float e0 = r.x * a0 + r.y * a1;
    float e1 = r.z * a0 + r.w * a1;
    e0 = (e0 > 0.0f) ? e0 : NEG_SLOPE * e0;
    e1 = (e1 > 0.0f) ? e1 : NEG_SLOPE * e1;
    float ex0 = __expf(e0);
    float ex1 = __expf(e1);

    int p0 = atomicAdd(&g_cnt[d2.x], 1);
    int p1 = atomicAdd(&g_cnt[d2.y], 1);
    if (p0 < BUCKET)
        g_csr[(size_t)d2.x * BUCKET + p0] = make_float2(__int_as_float(s2.x), ex0);
    if (p1 < BUCKET)
        g_csr[(size_t)d2.y * BUCKET + p1] = make_float2(__int_as_float(s2.y), ex1);
}

// ---------------------------------------------------------------------------
// GEMM core (R8-proven inner loop, single weight matrix).
// 64 nodes/block, 128 threads, thread = 4 cols x 8 nodes, packed f32x2 FMA.
// smem: dup feat [64][130] (33280 B) + transposed weights [64][64] (16384 B)
//     = 49664 B  ->  4 CTAs/SM.
// ---------------------------------------------------------------------------
#define GEMM_SMEM_BYTES (64 * 130 * 4 + 64 * 64 * 4)

template <bool SELF>
__device__ __forceinline__ void gemm_core(
    const float* __restrict__ feat,
    const float* __restrict__ W,
    const float* __restrict__ bs, const float* __restrict__ bn,
    float* __restrict__ out) {
    extern __shared__ float smem[];
    float (*sF2)[130] = (float(*)[130])smem;                 // dup feat [k][2n+h]
    float (*sW)[64]   = (float(*)[64])(smem + 64 * 130);     // transposed [k][o]

    const int t = threadIdx.x;
    const int nodeBase = blockIdx.x * 64;

    // Weights: transpose-store with XOR swizzle at float4 granularity.
    for (int i = t; i < 4096; i += 128) {
        int o = i >> 6, k = i & 63;
        int col = (o & 3) | ((((o >> 2) + (k & 15)) & 15) << 2);
        sW[k][col] = W[i];
    }
    // Feat: coalesced read, duplicated (v,v) transposed store.
    for (int i = t; i < 4096; i += 128) {
        int n = i >> 6, k = i & 63;
        int node = nodeBase + n;
        float v = (node < N_NODES) ? __ldg(&feat[(size_t)node * D + k]) : 0.f;
        *reinterpret_cast<float2*>(&sF2[k][n * 2]) = make_float2(v, v);
    }
    __syncthreads();

    const int oc = (t & 15) * 4;
    const int nr = t >> 4;

    ull acc[8][2] = {};

    #pragma unroll 8
    for (int k = 0; k < 64; k++) {
        const int g4 = (((oc >> 2) + (k & 15)) & 15) << 2;
        ulonglong2 w = *reinterpret_cast<const ulonglong2*>(&sW[k][g4]);
        const float* frow = &sF2[k][nr * 16];
        #pragma unroll
        for (int j = 0; j < 8; j++) {
            ull f = *reinterpret_cast<const ull*>(frow + j * 2);
            FMA2(acc[j][0], f, w.x);
            FMA2(acc[j][1], f, w.y);
        }
    }

    float b0 = 0.f, b1 = 0.f, b2 = 0.f, b3 = 0.f;
    if (SELF) {
        b0 = __ldg(&bs[oc])     + __ldg(&bn[oc]);
        b1 = __ldg(&bs[oc + 1]) + __ldg(&bn[oc + 1]);
        b2 = __ldg(&bs[oc + 2]) + __ldg(&bn[oc + 2]);
        b3 = __ldg(&bs[oc + 3]) + __ldg(&bn[oc + 3]);
    }

    #pragma unroll
    for (int j = 0; j < 8; j++) {
        int node = nodeBase + nr * 8 + j;
        if (node < N_NODES) {
            float v0, v1, v2, v3;
            UNPACK2(v0, v1, acc[j][0]);
            UNPACK2(v2, v3, acc[j][1]);
            if (SELF) {
                reinterpret_cast<float4*>(out)[(size_t)node * 16 + (oc >> 2)] =
                    make_float4(v0 + b0, v1 + b1, v2 + b2, v3 + b3);
            } else {
                __half2 h01 = __floats2half2_rn(v0, v1);
                __half2 h23 = __floats2half2_rn(v2, v3);
                *reinterpret_cast<uint2*>(&g_gh[(size_t)node * 32 + (oc >> 1)]) =
                    make_uint2(h2_bits(h01), h2_bits(h23));
            }
        }
    }
}

__global__ __launch_bounds__(128) void neigh_gemm_kernel(
    const float* __restrict__ feat, const float* __restrict__ Wn) {
    gemm_core<false>(feat, Wn, nullptr, nullptr, nullptr);
}

__global__ __launch_bounds__(128) void self_gemm_kernel(
    const float* __restrict__ feat, const float* __restrict__ Ws,
    const float* __restrict__ bs, const float* __restrict__ bn,
    float* __restrict__ out) {
    gemm_core<true>(feat, Ws, bs, bn, out);
}

// ---------------------------------------------------------------------------
// K3: gather-aggregate. One warp per dst node; CSR bucket register-cached
// (lane j holds edge j), shfl broadcasts -> all gathers issue back-to-back.
//   out[v] += (1/sum ex) * sum ex * g[src]
// ---------------------------------------------------------------------------
__global__ __launch_bounds__(256) void aggregate_kernel(float* __restrict__ out) {
    int warp = (blockIdx.x * blockDim.x + threadIdx.x) >> 5;
    if (warp >= N_NODES) return;
    const int lane = threadIdx.x & 31;

    int cnt = g_cnt[warp];
    if (cnt == 0) return;
    if (cnt > BUCKET) cnt = BUCKET;
    const float2* bucket = &g_csr[(size_t)warp * BUCKET];

    // Prefetch up to 32 edge records into lane registers (zero-pad lanes).
    const int n1 = (cnt < 32) ? cnt : 32;
    float2 myp = (lane < n1) ? __ldg(&bucket[lane]) : make_float2(0.f, 0.f);

    float ax = 0.f, ay = 0.f, sum = 0.f;

    // Register-broadcast main loop, 4 edges per step (zero-weight pads safe:
    // gather of g_gh[0] is valid, weight 0 contributes nothing).
    for (int j = 0; j < n1; j += 4) {
        float w0 = __shfl_sync(0xffffffffu, myp.y, j);
        float w1 = __shfl_sync(0xffffffffu, myp.y, j + 1);
        float w2 = __shfl_sync(0xffffffffu, myp.y, j + 2);
        float w3 = __shfl_sync(0xffffffffu, myp.y, j + 3);
        int   s0 = __shfl_sync(0xffffffffu, __float_as_int(myp.x), j);
        int   s1 = __shfl_sync(0xffffffffu, __float_as_int(myp.x), j + 1);
        int   s2 = __shfl_sync(0xffffffffu, __float_as_int(myp.x), j + 2);
        int   s3 = __shfl_sync(0xffffffffu, __float_as_int(myp.x), j + 3);
        float2 f0 = __half22float2(__ldg(&g_gh[(size_t)s0 * 32 + lane]));
        float2 f1 = __half22float2(__ldg(&g_gh[(size_t)s1 * 32 + lane]));
        float2 f2 = __half22float2(__ldg(&g_gh[(size_t)s2 * 32 + lane]));
        float2 f3 = __half22float2(__ldg(&g_gh[(size_t)s3 * 32 + lane]));
        sum += w0 + w1 + w2 + w3;
        ax  += w0 * f0.x + w1 * f1.x + w2 * f2.x + w3 * f3.x;
        ay  += w0 * f0.y + w1 * f1.y + w2 * f2.y + w3 * f3.y;
    }
    // Rare tail: degree > 32 (P ~ 2e-4 per node)
    for (int j = 32; j < cnt; j++) {
        float2 p = __ldg(&bucket[j]);
        float2 f = __half22float2(
            __ldg(&g_gh[(size_t)__float_as_int(p.x) * 32 + lane]));
        sum += p.y;
        ax  += p.y * f.x;
        ay  += p.y * f.y;
    }

    const float inv = 1.0f / sum;
    float2* po = reinterpret_cast<float2*>(out) + (size_t)warp * 32 + lane;
    float2 cur = *po;
    cur.x += ax * inv;
    cur.y += ay * inv;
    *po = cur;
}

// ---------------------------------------------------------------------------
// Launch: [neigh GEMM; self GEMM] on s2  ||  [memset; place] on main
//         join -> aggregate
// ---------------------------------------------------------------------------
extern "C" void kernel_launch(void* const* d_in, const int* in_sizes, int n_in,
                              void* d_out, int out_size) {
    const float* feat = (const float*)d_in[0];
    const float* rel  = (const float*)d_in[1];
    const float* Ws   = (const float*)d_in[2];
    const float* bs   = (const float*)d_in[3];
    const float* Wn   = (const float*)d_in[4];
    const float* bn   = (const float*)d_in[5];
    const float* attn = (const float*)d_in[6];
    const int*   src  = (const int*)d_in[7];
    const int*   dst  = (const int*)d_in[8];
    float* out = (float*)d_out;

    static void*        cnt_addr = nullptr;
    static cudaStream_t s2;
    static cudaEvent_t  evFork, evJoin;
    if (!cnt_addr) {
        cudaFuncSetAttribute(neigh_gemm_kernel,
                             cudaFuncAttributeMaxDynamicSharedMemorySize,
                             GEMM_SMEM_BYTES);
        cudaFuncSetAttribute(self_gemm_kernel,
                             cudaFuncAttributeMaxDynamicSharedMemorySize,
                             GEMM_SMEM_BYTES);
        cudaGetSymbolAddress(&cnt_addr, g_cnt);
        cudaStreamCreateWithFlags(&s2, cudaStreamNonBlocking);
        cudaEventCreateWithFlags(&evFork, cudaEventDisableTiming);
        cudaEventCreateWithFlags(&evJoin, cudaEventDisableTiming);
    }

    // Fork: node path (both GEMMs) on side stream
    cudaEventRecord(evFork, 0);
    cudaStreamWaitEvent(s2, evFork, 0);
    neigh_gemm_kernel<<<(N_NODES + 63) / 64, 128, GEMM_SMEM_BYTES, s2>>>(feat, Wn);
    self_gemm_kernel <<<(N_NODES + 63) / 64, 128, GEMM_SMEM_BYTES, s2>>>(
        feat, Ws, bs, bn, out);
    cudaEventRecord(evJoin, s2);

    // Edge path: zero counters, then single-pass bucket build
    cudaMemsetAsync(cnt_addr, 0, N_NODES * sizeof(int));
    place_kernel<<<(N_EDGES / 2 + 255) / 256, 256>>>(rel, attn, src, dst);

    // Join, then aggregate needs both paths
    cudaStreamWaitEvent(0, evJoin, 0);
    aggregate_kernel<<<(N_NODES * 32 + 255) / 256, 256>>>(out);
}

// round 11
// speedup vs baseline: 1.2564x; 1.1045x over previous
#include <cuda_runtime.h>
#include <cuda_fp16.h>
#include <cstdint>
#include <cstring>

#define N_NODES   100000
#define N_EDGES   1600000
#define D         64
#define NEG_SLOPE 0.2f
#define BUCKET    64        // max in-degree slots (Poisson(16): P(>64) ~ 1e-29)

typedef unsigned long long ull;

// packed fp32x2 FMA (sm_103a FFMA2 — PTX-only pattern)
#define FMA2(d, a, b) \
    asm("fma.rn.f32x2 %0, %1, %2, %0;" : "+l"(d) : "l"(a), "l"(b))
#define UNPACK2(lo, hi, in) \
    asm("mov.b64 {%0, %1}, %2;" : "=f"(lo), "=f"(hi) : "l"(in))
#define PACK2(out, lo, hi) \
    asm("mov.b64 %0, {%1, %2};" : "=l"(out) : "f"(lo), "f"(hi))

__device__ __forceinline__ uint32_t h2_bits(__half2 h) {
    uint32_t u;
    memcpy(&u, &h, 4);
    return u;
}
__device__ __forceinline__ __half2 bits_h2(uint32_t u) {
    __half2 h;
    memcpy(&h, &u, 4);
    return h;
}

// Scratch (allocation-free rule: __device__ globals)
__device__ int     g_cnt[N_NODES];                       // in-degree counters
__device__ float2  g_csr[(size_t)N_NODES * BUCKET];      // padded buckets (src, ex)
__device__ __half2 g_gh[(size_t)N_NODES * 32];           // feat @ W_neigh^T (fp16)

// ---------------------------------------------------------------------------
// K1: single-pass bucket build. pos = atomicAdd(cnt[d]); csr[d*64+pos]=(src,ex)
// ---------------------------------------------------------------------------
__global__ void place_kernel(const float* __restrict__ rel,
                             const float* __restrict__ attn,
                             const int*   __restrict__ src,
                             const int*   __restrict__ dst) {
    int i = (blockIdx.x * blockDim.x + threadIdx.x) * 2;
    if (i >= N_EDGES) return;
    float a0 = __ldg(&attn[0]);
    float a1 = __ldg(&attn[1]);
    float4 r = *reinterpret_cast<const float4*>(rel + i * 2);  // edges i, i+1
    int2 s2 = *reinterpret_cast<const int2*>(src + i);
    int2 d2 = *reinterpret_cast<const int2*>(dst + i);

    float e0 = r.x * a0 + r.y * a1;
    float e1 = r.z * a0 + r.w * a1;
    e0 = (e0 > 0.0f) ? e0 : NEG_SLOPE * e0;
    e1 = (e1 > 0.0f) ? e1 : NEG_SLOPE * e1;
    float ex0 = __expf(e0);
    float ex1 = __expf(e1);

    int p0 = atomicAdd(&g_cnt[d2.x], 1);
    int p1 = atomicAdd(&g_cnt[d2.y], 1);
    if (p0 < BUCKET)
        g_csr[(size_t)d2.x * BUCKET + p0] = make_float2(__int_as_float(s2.x), ex0);
    if (p1 < BUCKET)
        g_csr[(size_t)d2.y * BUCKET + p1] = make_float2(__int_as_float(s2.y), ex1);
}

// ---------------------------------------------------------------------------
// GEMM core (R8-proven inner loop, single weight matrix).
// 64 nodes/block, 128 threads, thread = 4 cols x 8 nodes, packed f32x2 FMA.
// SELF variant contributes into zeroed `out` with red.add (order-free vs
// aggregate); neigh variant stores fp16 rows to g_gh.
// ---------------------------------------------------------------------------
#define GEMM_SMEM_BYTES (64 * 130 * 4 + 64 * 64 * 4)    // 49664 B -> 4 CTA/SM

template <bool SELF>
__device__ __forceinline__ void gemm_core(
    const float* __restrict__ feat,
    const float* __restrict__ W,
    const float* __restrict__ bs, const float* __restrict__ bn,
    float* __restrict__ out) {
    extern __shared__ float smem[];
    float (*sF2)[130] = (float(*)[130])smem;                 // dup feat [k][2n+h]
    float (*sW)[64]   = (float(*)[64])(smem + 64 * 130);     // transposed [k][o]

    const int t = threadIdx.x;
    const int nodeBase = blockIdx.x * 64;

    for (int i = t; i < 4096; i += 128) {
        int o = i >> 6, k = i & 63;
        int col = (o & 3) | ((((o >> 2) + (k & 15)) & 15) << 2);
        sW[k][col] = W[i];
    }
    for (int i = t; i < 4096; i += 128) {
        int n = i >> 6, k = i & 63;
        int node = nodeBase + n;
        float v = (node < N_NODES) ? __ldg(&feat[(size_t)node * D + k]) : 0.f;
        *reinterpret_cast<float2*>(&sF2[k][n * 2]) = make_float2(v, v);
    }
    __syncthreads();

    const int oc = (t & 15) * 4;
    const int nr = t >> 4;

    ull acc[8][2] = {};

    #pragma unroll 8
    for (int k = 0; k < 64; k++) {
        const int g4 = (((oc >> 2) + (k & 15)) & 15) << 2;
        ulonglong2 w = *reinterpret_cast<const ulonglong2*>(&sW[k][g4]);
        const float* frow = &sF2[k][nr * 16];
        #pragma unroll
        for (int j = 0; j < 8; j++) {
            ull f = *reinterpret_cast<const ull*>(frow + j * 2);
            FMA2(acc[j][0], f, w.x);
            FMA2(acc[j][1], f, w.y);
        }
    }

    float b0 = 0.f, b1 = 0.f, b2 = 0.f, b3 = 0.f;
    if (SELF) {
        b0 = __ldg(&bs[oc])     + __ldg(&bn[oc]);
        b1 = __ldg(&bs[oc + 1]) + __ldg(&bn[oc + 1]);
        b2 = __ldg(&bs[oc + 2]) + __ldg(&bn[oc + 2]);
        b3 = __ldg(&bs[oc + 3]) + __ldg(&bn[oc + 3]);
    }

    #pragma unroll
    for (int j = 0; j < 8; j++) {
        int node = nodeBase + nr * 8 + j;
        if (node < N_NODES) {
            float v0, v1, v2, v3;
            UNPACK2(v0, v1, acc[j][0]);
            UNPACK2(v2, v3, acc[j][1]);
            if (SELF) {
                float* p = out + (size_t)node * D + oc;
                asm volatile("red.global.add.v4.f32 [%0], {%1,%2,%3,%4};"
                             :: "l"(p), "f"(v0 + b0), "f"(v1 + b1),
                                "f"(v2 + b2), "f"(v3 + b3) : "memory");
            } else {
                __half2 h01 = __floats2half2_rn(v0, v1);
                __half2 h23 = __floats2half2_rn(v2, v3);
                *reinterpret_cast<uint2*>(&g_gh[(size_t)node * 32 + (oc >> 1)]) =
                    make_uint2(h2_bits(h01), h2_bits(h23));
            }
        }
    }
}

__global__ __launch_bounds__(128) void neigh_gemm_kernel(
    const float* __restrict__ feat, const float* __restrict__ Wn) {
    gemm_core<false>(feat, Wn, nullptr, nullptr, nullptr);
}

__global__ __launch_bounds__(128) void self_gemm_kernel(
    const float* __restrict__ feat, const float* __restrict__ Ws,
    const float* __restrict__ bs, const float* __restrict__ bn,
    float* __restrict__ out) {
    gemm_core<true>(feat, Ws, bs, bn, out);
}

// ---------------------------------------------------------------------------
// K3: gather-aggregate v3. Warp per node, 16 lanes per edge, 2 edges/step.
//   lane = h*16 + c : half h handles edge j+h, dim group c (dims 4c..4c+3).
//   Contribution added to zeroed out via red.add (order-free vs self GEMM).
// ---------------------------------------------------------------------------
__global__ __launch_bounds__(256) void aggregate_kernel(float* __restrict__ out) {
    int warp = (blockIdx.x * blockDim.x + threadIdx.x) >> 5;
    if (warp >= N_NODES) return;
    const int lane = threadIdx.x & 31;
    const int h = lane >> 4;       // which edge of the pair
    const int c = lane & 15;       // dim group

    int cnt = g_cnt[warp];
    if (cnt == 0) return;
    if (cnt > BUCKET) cnt = BUCKET;
    const float2* bucket = &g_csr[(size_t)warp * BUCKET];

    ull accA = 0, accB = 0;
    float sum = 0.f;

    #pragma unroll 2
    for (int j = 0; j < cnt; j += 2) {
        int idx = j + h;
        float2 p = (idx < cnt) ? __ldg(&bucket[idx])
                               : make_float2(__int_as_float(0), 0.f);
        int   s = __float_as_int(p.x);
        float w = p.y;
        uint2 hv = __ldg(reinterpret_cast<const uint2*>(
            &g_gh[(size_t)s * 32 + c * 2]));          // 4 dims, 8B, contiguous
        float2 fa = __half22float2(bits_h2(hv.x));
        float2 fb = __half22float2(bits_h2(hv.y));
        ull fa64, fb64, wd;
        PACK2(fa64, fa.x, fa.y);
        PACK2(fb64, fb.x, fb.y);
        PACK2(wd, w, w);
        FMA2(accA, fa64, wd);
        FMA2(accB, fb64, wd);
        sum += w;
    }

    float a0, a1, a2, a3;
    UNPACK2(a0, a1, accA);
    UNPACK2(a2, a3, accB);
    a0  += __shfl_xor_sync(0xffffffffu, a0, 16);
    a1  += __shfl_xor_sync(0xffffffffu, a1, 16);
    a2  += __shfl_xor_sync(0xffffffffu, a2, 16);
    a3  += __shfl_xor_sync(0xffffffffu, a3, 16);
    sum += __shfl_xor_sync(0xffffffffu, sum, 16);

    if (h == 0) {
        float inv = 1.0f / sum;
        float* p = out + (size_t)warp * D + c * 4;
        asm volatile("red.global.add.v4.f32 [%0], {%1,%2,%3,%4};"
                     :: "l"(p), "f"(a0 * inv), "f"(a1 * inv),
                        "f"(a2 * inv), "f"(a3 * inv) : "memory");
    }
}

// ---------------------------------------------------------------------------
// Launch schedule (out zeroed; self GEMM and aggregate RED-add in any order):
//   s2:   neigh_gemm --evNeigh--> (wait evMemset) self_gemm --evJoin-->
//   main: memset cnt, memset out --evMemset--> place --(wait evNeigh)-->
//         aggregate --(wait evJoin)
// ---------------------------------------------------------------------------
extern "C" void kernel_launch(void* const* d_in, const int* in_sizes, int n_in,
                              void* d_out, int out_size) {
    const float* feat = (const float*)d_in[0];
    const float* rel  = (const float*)d_in[1];
    const float* Ws   = (const float*)d_in[2];
    const float* bs   = (const float*)d_in[3];
    const float* Wn   = (const float*)d_in[4];
    const float* bn   = (const float*)d_in[5];
    const float* attn = (const float*)d_in[6];
    const int*   src  = (const int*)d_in[7];
    const int*   dst  = (const int*)d_in[8];
    float* out = (float*)d_out;

    static void*        cnt_addr = nullptr;
    static cudaStream_t s2;
    static cudaEvent_t  evFork, evNeigh, evMemset, evJoin;
    if (!cnt_addr) {
        cudaFuncSetAttribute(neigh_gemm_kernel,
                             cudaFuncAttributeMaxDynamicSharedMemorySize,
                             GEMM_SMEM_BYTES);
        cudaFuncSetAttribute(self_gemm_kernel,
                             cudaFuncAttributeMaxDynamicSharedMemorySize,
                             GEMM_SMEM_BYTES);
        cudaGetSymbolAddress(&cnt_addr, g_cnt);
        cudaStreamCreateWithFlags(&s2, cudaStreamNonBlocking);
        cudaEventCreateWithFlags(&evFork,   cudaEventDisableTiming);
        cudaEventCreateWithFlags(&evNeigh,  cudaEventDisableTiming);
        cudaEventCreateWithFlags(&evMemset, cudaEventDisableTiming);
        cudaEventCreateWithFlags(&evJoin,   cudaEventDisableTiming);
    }

    // Fork side stream
    cudaEventRecord(evFork, 0);
    cudaStreamWaitEvent(s2, evFork, 0);
    neigh_gemm_kernel<<<(N_NODES + 63) / 64, 128, GEMM_SMEM_BYTES, s2>>>(feat, Wn);
    cudaEventRecord(evNeigh, s2);

    // Main: zero counters and output, then bucket build
    cudaMemsetAsync(cnt_addr, 0, N_NODES * sizeof(int));
    cudaMemsetAsync(out, 0, (size_t)N_NODES * D * sizeof(float));
    cudaEventRecord(evMemset, 0);
    place_kernel<<<(N_EDGES / 2 + 255) / 256, 256>>>(rel, attn, src, dst);

    // Side stream: self GEMM REDs into out (needs out zeroed)
    cudaStreamWaitEvent(s2, evMemset, 0);
    self_gemm_kernel<<<(N_NODES + 63) / 64, 128, GEMM_SMEM_BYTES, s2>>>(
        feat, Ws, bs, bn, out);
    cudaEventRecord(evJoin, s2);

    // Aggregate needs neigh GEMM + buckets; overlaps with self GEMM
    cudaStreamWaitEvent(0, evNeigh, 0);
    aggregate_kernel<<<(N_NODES * 32 + 255) / 256, 256>>>(out);

    // Final join: self GEMM must complete before harness reads out
    cudaStreamWaitEvent(0, evJoin, 0);
}

// round 12
// speedup vs baseline: 1.3401x; 1.0666x over previous
#include <cuda_runtime.h>
#include <cuda_fp16.h>
#include <cstdint>
#include <cstring>

#define N_NODES   100000
#define N_EDGES   1600000
#define D         64
#define NEG_SLOPE 0.2f
#define BUCKET    64        // max in-degree slots (Poisson(16): P(>64) ~ 1e-29)

typedef unsigned long long ull;

// packed fp32x2 FMA (sm_103a FFMA2 — PTX-only pattern)
#define FMA2(d, a, b) \
    asm("fma.rn.f32x2 %0, %1, %2, %0;" : "+l"(d) : "l"(a), "l"(b))
#define UNPACK2(lo, hi, in) \
    asm("mov.b64 {%0, %1}, %2;" : "=f"(lo), "=f"(hi) : "l"(in))
// packed fp16x2 FMA / ADD
#define HFMA2(d, a, b) \
    asm("fma.rn.f16x2 %0, %1, %2, %0;" : "+r"(d) : "r"(a), "r"(b))
#define HADD2(d, a, b) \
    asm("add.rn.f16x2 %0, %1, %2;" : "=r"(d) : "r"(a), "r"(b))

__device__ __forceinline__ uint32_t h2_bits(__half2 h) {
    uint32_t u;
    memcpy(&u, &h, 4);
    return u;
}
__device__ __forceinline__ __half2 bits_h2(uint32_t u) {
    __half2 h;
    memcpy(&h, &u, 4);
    return h;
}

// Scratch (allocation-free rule: __device__ globals)
__device__ int     g_cnt[N_NODES];                       // in-degree counters
__device__ float2  g_csr[(size_t)N_NODES * BUCKET];      // padded buckets (src, ex)
__device__ __half2 g_gh[(size_t)N_NODES * 32];           // feat @ W_neigh^T (fp16)

// ---------------------------------------------------------------------------
// K1: single-pass bucket build. pos = atomicAdd(cnt[d]); csr[d*64+pos]=(src,ex)
// ---------------------------------------------------------------------------
__global__ void place_kernel(const float* __restrict__ rel,
                             const float* __restrict__ attn,
                             const int*   __restrict__ src,
                             const int*   __restrict__ dst) {
    int i = (blockIdx.x * blockDim.x + threadIdx.x) * 2;
    if (i >= N_EDGES) return;
    float a0 = __ldg(&attn[0]);
    float a1 = __ldg(&attn[1]);
    float4 r = *reinterpret_cast<const float4*>(rel + i * 2);  // edges i, i+1
    int2 s2 = *reinterpret_cast<const int2*>(src + i);
    int2 d2 = *reinterpret_cast<const int2*>(dst + i);

    float e0 = r.x * a0 + r.y * a1;
    float e1 = r.z * a0 + r.w * a1;
    e0 = (e0 > 0.0f) ? e0 : NEG_SLOPE * e0;
    e1 = (e1 > 0.0f) ? e1 : NEG_SLOPE * e1;
    float ex0 = __expf(e0);
    float ex1 = __expf(e1);

    int p0 = atomicAdd(&g_cnt[d2.x], 1);
    int p1 = atomicAdd(&g_cnt[d2.y], 1);
    if (p0 < BUCKET)
        g_csr[(size_t)d2.x * BUCKET + p0] = make_float2(__int_as_float(s2.x), ex0);
    if (p1 < BUCKET)
        g_csr[(size_t)d2.y * BUCKET + p1] = make_float2(__int_as_float(s2.y), ex1);
}

// ---------------------------------------------------------------------------
// GEMM core (R8-proven inner loop, single weight matrix).
// 64 nodes/block, 128 threads, thread = 4 cols x 8 nodes, packed f32x2 FMA.
// SELF variant RED-adds into zeroed `out` (order-free vs aggregate);
// neigh variant stores fp16 rows to g_gh.
// ---------------------------------------------------------------------------
#define GEMM_SMEM_BYTES (64 * 130 * 4 + 64 * 64 * 4)    // 49664 B -> 4 CTA/SM

template <bool SELF>
__device__ __forceinline__ void gemm_core(
    const float* __restrict__ feat,
    const float* __restrict__ W,
    const float* __restrict__ bs, const float* __restrict__ bn,
    float* __restrict__ out) {
    extern __shared__ float smem[];
    float (*sF2)[130] = (float(*)[130])smem;                 // dup feat [k][2n+h]
    float (*sW)[64]   = (float(*)[64])(smem + 64 * 130);     // transposed [k][o]

    const int t = threadIdx.x;
    const int nodeBase = blockIdx.x * 64;

    for (int i = t; i < 4096; i += 128) {
        int o = i >> 6, k = i & 63;
        int col = (o & 3) | ((((o >> 2) + (k & 15)) & 15) << 2);
        sW[k][col] = W[i];
    }
    for (int i = t; i < 4096; i += 128) {
        int n = i >> 6, k = i & 63;
        int node = nodeBase + n;
        float v = (node < N_NODES) ? __ldg(&feat[(size_t)node * D + k]) : 0.f;
        *reinterpret_cast<float2*>(&sF2[k][n * 2]) = make_float2(v, v);
    }
    __syncthreads();

    const int oc = (t & 15) * 4;
    const int nr = t >> 4;

    ull acc[8][2] = {};

    #pragma unroll 8
    for (int k = 0; k < 64; k++) {
        const int g4 = (((oc >> 2) + (k & 15)) & 15) << 2;
        ulonglong2 w = *reinterpret_cast<const ulonglong2*>(&sW[k][g4]);
        const float* frow = &sF2[k][nr * 16];
        #pragma unroll
        for (int j = 0; j < 8; j++) {
            ull f = *reinterpret_cast<const ull*>(frow + j * 2);
            FMA2(acc[j][0], f, w.x);
            FMA2(acc[j][1], f, w.y);
        }
    }

    float b0 = 0.f, b1 = 0.f, b2 = 0.f, b3 = 0.f;
    if (SELF) {
        b0 = __ldg(&bs[oc])     + __ldg(&bn[oc]);
        b1 = __ldg(&bs[oc + 1]) + __ldg(&bn[oc + 1]);
        b2 = __ldg(&bs[oc + 2]) + __ldg(&bn[oc + 2]);
        b3 = __ldg(&bs[oc + 3]) + __ldg(&bn[oc + 3]);
    }

    #pragma unroll
    for (int j = 0; j < 8; j++) {
        int node = nodeBase + nr * 8 + j;
        if (node < N_NODES) {
            float v0, v1, v2, v3;
            UNPACK2(v0, v1, acc[j][0]);
            UNPACK2(v2, v3, acc[j][1]);
            if (SELF) {
                float* p = out + (size_t)node * D + oc;
                asm volatile("red.global.add.v4.f32 [%0], {%1,%2,%3,%4};"
                             :: "l"(p), "f"(v0 + b0), "f"(v1 + b1),
                                "f"(v2 + b2), "f"(v3 + b3) : "memory");
            } else {
                __half2 h01 = __floats2half2_rn(v0, v1);
                __half2 h23 = __floats2half2_rn(v2, v3);
                *reinterpret_cast<uint2*>(&g_gh[(size_t)node * 32 + (oc >> 1)]) =
                    make_uint2(h2_bits(h01), h2_bits(h23));
            }
        }
    }
}

__global__ __launch_bounds__(128) void neigh_gemm_kernel(
    const float* __restrict__ feat, const float* __restrict__ Wn) {
    gemm_core<false>(feat, Wn, nullptr, nullptr, nullptr);
}

__global__ __launch_bounds__(128) void self_gemm_kernel(
    const float* __restrict__ feat, const float* __restrict__ Ws,
    const float* __restrict__ bs, const float* __restrict__ bn,
    float* __restrict__ out) {
    gemm_core<true>(feat, Ws, bs, bn, out);
}

// ---------------------------------------------------------------------------
// K3: gather-aggregate v4 — fp16 HFMA2 accumulation.
//   Warp per node; lane = h*8 + c : h = edge slot (4 edges/step),
//   c = dim group (8 dims = one LDG.128). Only ~cnt/4 fp16 adds per acc.
//   Contribution RED-added to zeroed out (order-free vs self GEMM).
// ---------------------------------------------------------------------------
__global__ __launch_bounds__(256) void aggregate_kernel(float* __restrict__ out) {
    int warp = (blockIdx.x * blockDim.x + threadIdx.x) >> 5;
    if (warp >= N_NODES) return;
    const int lane = threadIdx.x & 31;
    const int h = lane >> 3;       // edge slot 0..3
    const int c = lane & 7;        // dim group (8 dims)

    int cnt = g_cnt[warp];
    if (cnt == 0) return;
    if (cnt > BUCKET) cnt = BUCKET;
    const float2* bucket = &g_csr[(size_t)warp * BUCKET];

    uint32_t acc0 = 0, acc1 = 0, acc2 = 0, acc3 = 0;   // half2 accumulators
    float sum = 0.f;

    #pragma unroll 2
    for (int j = 0; j < cnt; j += 4) {
        int idx = j + h;
        float2 p = (idx < cnt) ? __ldg(&bucket[idx])
                               : make_float2(__int_as_float(0), 0.f);
        int   s = __float_as_int(p.x);
        float w = p.y;                       // 0 for pad lanes -> no contribution
        uint4 hv = __ldg(reinterpret_cast<const uint4*>(
            &g_gh[(size_t)s * 32 + c * 4])); // 8 dims, 16B aligned
        uint32_t wh = h2_bits(__float2half2_rn(w));
        HFMA2(acc0, hv.x, wh);
        HFMA2(acc1, hv.y, wh);
        HFMA2(acc2, hv.z, wh);
        HFMA2(acc3, hv.w, wh);
        sum += w;
    }

    // Combine the 4 edge slots (h) in fp16 via shfl-xor 8, 16
    uint32_t o0, o1, o2, o3;
    o0 = __shfl_xor_sync(0xffffffffu, acc0, 8);  HADD2(acc0, acc0, o0);
    o1 = __shfl_xor_sync(0xffffffffu, acc1, 8);  HADD2(acc1, acc1, o1);
    o2 = __shfl_xor_sync(0xffffffffu, acc2, 8);  HADD2(acc2, acc2, o2);
    o3 = __shfl_xor_sync(0xffffffffu, acc3, 8);  HADD2(acc3, acc3, o3);
    o0 = __shfl_xor_sync(0xffffffffu, acc0, 16); HADD2(acc0, acc0, o0);
    o1 = __shfl_xor_sync(0xffffffffu, acc1, 16); HADD2(acc1, acc1, o1);
    o2 = __shfl_xor_sync(0xffffffffu, acc2, 16); HADD2(acc2, acc2, o2);
    o3 = __shfl_xor_sync(0xffffffffu, acc3, 16); HADD2(acc3, acc3, o3);
    sum += __shfl_xor_sync(0xffffffffu, sum, 8);
    sum += __shfl_xor_sync(0xffffffffu, sum, 16);

    if (h == 0) {
        const float inv = 1.0f / sum;
        float2 f0 = __half22float2(bits_h2(acc0));
        float2 f1 = __half22float2(bits_h2(acc1));
        float2 f2 = __half22float2(bits_h2(acc2));
        float2 f3 = __half22float2(bits_h2(acc3));
        float* p = out + (size_t)warp * D + c * 8;
        asm volatile("red.global.add.v4.f32 [%0], {%1,%2,%3,%4};"
                     :: "l"(p), "f"(f0.x * inv), "f"(f0.y * inv),
                        "f"(f1.x * inv), "f"(f1.y * inv) : "memory");
        asm volatile("red.global.add.v4.f32 [%0], {%1,%2,%3,%4};"
                     :: "l"(p + 4), "f"(f2.x * inv), "f"(f2.y * inv),
                        "f"(f3.x * inv), "f"(f3.y * inv) : "memory");
    }
}

// ---------------------------------------------------------------------------
// Launch schedule (out zeroed; self GEMM and aggregate RED-add in any order):
//   s2:   neigh_gemm --evNeigh--> (wait evMemset) self_gemm --evJoin-->
//   main: memset cnt, memset out --evMemset--> place --(wait evNeigh)-->
//         aggregate --(wait evJoin)
// ---------------------------------------------------------------------------
extern "C" void kernel_launch(void* const* d_in, const int* in_sizes, int n_in,
                              void* d_out, int out_size) {
    const float* feat = (const float*)d_in[0];
    const float* rel  = (const float*)d_in[1];
    const float* Ws   = (const float*)d_in[2];
    const float* bs   = (const float*)d_in[3];
    const float* Wn   = (const float*)d_in[4];
    const float* bn   = (const float*)d_in[5];
    const float* attn = (const float*)d_in[6];
    const int*   src  = (const int*)d_in[7];
    const int*   dst  = (const int*)d_in[8];
    float* out = (float*)d_out;

    static void*        cnt_addr = nullptr;
    static cudaStream_t s2;
    static cudaEvent_t  evFork, evNeigh, evMemset, evJoin;
    if (!cnt_addr) {
        cudaFuncSetAttribute(neigh_gemm_kernel,
                             cudaFuncAttributeMaxDynamicSharedMemorySize,
                             GEMM_SMEM_BYTES);
        cudaFuncSetAttribute(self_gemm_kernel,
                             cudaFuncAttributeMaxDynamicSharedMemorySize,
                             GEMM_SMEM_BYTES);
        cudaGetSymbolAddress(&cnt_addr, g_cnt);
        cudaStreamCreateWithFlags(&s2, cudaStreamNonBlocking);
        cudaEventCreateWithFlags(&evFork,   cudaEventDisableTiming);
        cudaEventCreateWithFlags(&evNeigh,  cudaEventDisableTiming);
        cudaEventCreateWithFlags(&evMemset, cudaEventDisableTiming);
        cudaEventCreateWithFlags(&evJoin,   cudaEventDisableTiming);
    }

    // Fork side stream
    cudaEventRecord(evFork, 0);
    cudaStreamWaitEvent(s2, evFork, 0);
    neigh_gemm_kernel<<<(N_NODES + 63) / 64, 128, GEMM_SMEM_BYTES, s2>>>(feat, Wn);
    cudaEventRecord(evNeigh, s2);

    // Main: zero counters and output, then bucket build
    cudaMemsetAsync(cnt_addr, 0, N_NODES * sizeof(int));
    cudaMemsetAsync(out, 0, (size_t)N_NODES * D * sizeof(float));
    cudaEventRecord(evMemset, 0);
    place_kernel<<<(N_EDGES / 2 + 255) / 256, 256>>>(rel, attn, src, dst);

    // Side stream: self GEMM REDs into out (needs out zeroed)
    cudaStreamWaitEvent(s2, evMemset, 0);
    self_gemm_kernel<<<(N_NODES + 63) / 64, 128, GEMM_SMEM_BYTES, s2>>>(
        feat, Ws, bs, bn, out);
    cudaEventRecord(evJoin, s2);

    // Aggregate needs neigh GEMM + buckets; overlaps with self GEMM
    cudaStreamWaitEvent(0, evNeigh, 0);
    aggregate_kernel<<<(N_NODES * 32 + 255) / 256, 256>>>(out);

    // Final join: self GEMM must complete before harness reads out
    cudaStreamWaitEvent(0, evJoin, 0);
}